// round 4
// baseline (speedup 1.0000x reference)
#include <cuda_runtime.h>
#include <cuda_fp16.h>
#include <math.h>

constexpr int Bq   = 4;
constexpr int Nq   = 64;
constexpr int Fq   = 64;
constexpr int FINq = 32;
constexpr int EDIMq= 32;
constexpr int FFq  = Fq * Fq;          // 4096
constexpr int ROWS = Bq * Nq;          // 256 target rows (b,n)

__device__ float  g_H[ROWS * Fq];
__device__ int    g_cnt[ROWS];
__device__ int    g_midx[ROWS * Nq];
__device__ __half g_Amat[(size_t)ROWS * Nq * FFq];     // fp16 edge matrices

__device__ __forceinline__ float sigm(float x) { return 1.0f / (1.0f + expf(-x)); }

__device__ __forceinline__ unsigned long long pack2(float lo, float hi) {
    unsigned long long r;
    asm("mov.b64 %0, {%1, %2};" : "=l"(r) : "f"(lo), "f"(hi));
    return r;
}
__device__ __forceinline__ void unpack2(unsigned long long v, float& lo, float& hi) {
    asm("mov.b64 {%0, %1}, %2;" : "=f"(lo), "=f"(hi) : "l"(v));
}
__device__ __forceinline__ unsigned long long ffma2(
    unsigned long long a, unsigned long long b, unsigned long long c) {
    unsigned long long d;
    asm("fma.rn.f32x2 %0, %1, %2, %3;" : "=l"(d) : "l"(a), "l"(b), "l"(c));
    return d;
}

// ---------------------------------------------------------------------------
// Kernel 1: H0 = relu(X@W_embed + b) and per-row mask compaction
// ---------------------------------------------------------------------------
__global__ __launch_bounds__(64) void k_embed(
    const float* __restrict__ X, const float* __restrict__ A,
    const float* __restrict__ W_embed, const float* __restrict__ b_embed,
    float* __restrict__ Hout)
{
    int row = blockIdx.x;
    int t = threadIdx.x;
    __shared__ float xs[FINq];
    if (t < FINq) xs[t] = X[row * FINq + t];
    __syncthreads();

    float acc = b_embed[t];
#pragma unroll
    for (int k = 0; k < FINq; k++) acc += xs[k] * W_embed[k * Fq + t];
    Hout[row * Fq + t] = fmaxf(acc, 0.0f);

    if (t == 0) {
        const float* Arow = A + (size_t)row * Nq;
        int c = 0;
        for (int m = 0; m < Nq; m++)
            if (Arow[m] > 0.5f) g_midx[row * Nq + (c++)] = m;
        g_cnt[row] = c;
    }
}

// ---------------------------------------------------------------------------
// Kernel 2: edge matrices for ACTIVE edges, f32x2 FMA, vectorized smem reads.
// Each block: 2 target rows x 512 output columns, 4-edge unroll.
// ---------------------------------------------------------------------------
__global__ __launch_bounds__(256) void k_edge(
    const float* __restrict__ E, const float* __restrict__ W_edge,
    const float* __restrict__ b_edge)
{
    int rp = blockIdx.x;
    int c0 = blockIdx.y * 512;
    int t  = threadIdx.x;

    __shared__ unsigned long long Es2[2 * Nq][EDIMq];   // duplicated-pair E (32KB)
    __shared__ int   s_slot[2 * Nq];
    __shared__ int   s_ne;

    if (t == 0) {
        int ne = 0;
        for (int r = 0; r < 2; r++) {
            int row = rp * 2 + r;
            int cnt = g_cnt[row];
            for (int k = 0; k < cnt; k++) s_slot[ne++] = row * Nq + k;
        }
        s_ne = ne;
    }
    __syncthreads();
    int ne = s_ne;

    for (int i = t; i < ne * EDIMq; i += 256) {
        int kk = i >> 5, e = i & 31;
        int slot = s_slot[kk];
        int row  = slot >> 6;
        int m    = g_midx[slot];
        float v  = E[((size_t)row * Nq + m) * EDIMq + e];
        Es2[kk][e] = pack2(v, v);
    }
    __syncthreads();

    int cp = c0 + 2 * t;
    unsigned long long w01[EDIMq];
#pragma unroll
    for (int e = 0; e < EDIMq; e++) {
        float2 wv = reinterpret_cast<const float2*>(W_edge + (size_t)e * FFq + cp)[0];
        w01[e] = pack2(wv.x, wv.y);
    }
    float2 bv = reinterpret_cast<const float2*>(b_edge + cp)[0];
    unsigned long long bias01 = pack2(bv.x, bv.y);

    __half2* Aout = reinterpret_cast<__half2*>(g_Amat);
    int cidx = cp >> 1;

    int kk = 0;
    for (; kk + 4 <= ne; kk += 4) {
        unsigned long long acc0 = bias01, acc1 = bias01, acc2 = bias01, acc3 = bias01;
#pragma unroll
        for (int e = 0; e < EDIMq; e += 2) {
            ulonglong2 e0 = *reinterpret_cast<const ulonglong2*>(&Es2[kk + 0][e]);
            ulonglong2 e1 = *reinterpret_cast<const ulonglong2*>(&Es2[kk + 1][e]);
            ulonglong2 e2 = *reinterpret_cast<const ulonglong2*>(&Es2[kk + 2][e]);
            ulonglong2 e3 = *reinterpret_cast<const ulonglong2*>(&Es2[kk + 3][e]);
            acc0 = ffma2(e0.x, w01[e], acc0); acc0 = ffma2(e0.y, w01[e + 1], acc0);
            acc1 = ffma2(e1.x, w01[e], acc1); acc1 = ffma2(e1.y, w01[e + 1], acc1);
            acc2 = ffma2(e2.x, w01[e], acc2); acc2 = ffma2(e2.y, w01[e + 1], acc2);
            acc3 = ffma2(e3.x, w01[e], acc3); acc3 = ffma2(e3.y, w01[e + 1], acc3);
        }
        float x0, y0, x1, y1, x2, y2, x3, y3;
        unpack2(acc0, x0, y0); unpack2(acc1, x1, y1);
        unpack2(acc2, x2, y2); unpack2(acc3, x3, y3);
        Aout[(size_t)s_slot[kk + 0] * (FFq / 2) + cidx] = __floats2half2_rn(fmaxf(x0, 0.f), fmaxf(y0, 0.f));
        Aout[(size_t)s_slot[kk + 1] * (FFq / 2) + cidx] = __floats2half2_rn(fmaxf(x1, 0.f), fmaxf(y1, 0.f));
        Aout[(size_t)s_slot[kk + 2] * (FFq / 2) + cidx] = __floats2half2_rn(fmaxf(x2, 0.f), fmaxf(y2, 0.f));
        Aout[(size_t)s_slot[kk + 3] * (FFq / 2) + cidx] = __floats2half2_rn(fmaxf(x3, 0.f), fmaxf(y3, 0.f));
    }
    for (; kk < ne; kk++) {
        unsigned long long acc0 = bias01;
#pragma unroll
        for (int e = 0; e < EDIMq; e += 2) {
            ulonglong2 e0 = *reinterpret_cast<const ulonglong2*>(&Es2[kk][e]);
            acc0 = ffma2(e0.x, w01[e], acc0); acc0 = ffma2(e0.y, w01[e + 1], acc0);
        }
        float x0, y0;
        unpack2(acc0, x0, y0);
        Aout[(size_t)s_slot[kk] * (FFq / 2) + cidx] = __floats2half2_rn(fmaxf(x0, 0.f), fmaxf(y0, 0.f));
    }
}

// ---------------------------------------------------------------------------
// Kernel 3: one round, TWO rows per block (grid=128 -> single wave).
// Per row: 512 threads, thread = i*8 + q ; per edge ONE uint4 (8 fp16) load.
// 8-deep edge unroll for MLP. GRU fused, math fp32.
// ---------------------------------------------------------------------------
__global__ __launch_bounds__(1024) void k_round(
    const float* __restrict__ Hin, float* __restrict__ Hout,
    const float* __restrict__ gk, const float* __restrict__ grk,
    const float* __restrict__ gb, const float* __restrict__ grb)
{
    int t  = threadIdx.x;
    int tr = t >> 9;                 // which of the 2 rows
    int tt = t & 511;
    int row = blockIdx.x * 2 + tr;
    int b = row >> 6;

    __shared__ float4 Hs4[2][Nq][16];      // 32KB source states
    __shared__ float agg[2][Fq];
    __shared__ float xold[2][Fq];
    __shared__ float pg[2][2][2][3 * Fq];  // [row][x/h][split][gate] 12KB
    __shared__ float xg[2][3 * Fq], hg[2][3 * Fq];
    __shared__ float h1[2][Fq];

    int cnt = g_cnt[row];

    for (int idx = tt; idx < cnt * 16; idx += 512) {
        int kk = idx >> 4, qq = idx & 15;
        int m = g_midx[row * Nq + kk];
        Hs4[tr][kk][qq] = reinterpret_cast<const float4*>(Hin)[((size_t)b * Nq + m) * 16 + qq];
    }
    if (tt < Fq) xold[tr][tt] = Hin[(size_t)row * Fq + tt];
    __syncthreads();

    // ---- message aggregation ----
    int i = tt >> 3, q = tt & 7;     // i: output feature, q: 8-half chunk
    const uint4* Abase = reinterpret_cast<const uint4*>(g_Amat)
                       + (size_t)row * Nq * (FFq / 8) + i * 8 + q;
    float acc = 0.0f;

    auto dot8 = [&](const uint4& a, int kk) {
        const float4& hA = Hs4[tr][kk][q * 2];
        const float4& hB = Hs4[tr][kk][q * 2 + 1];
        float2 f0 = __half22float2(*reinterpret_cast<const __half2*>(&a.x));
        float2 f1 = __half22float2(*reinterpret_cast<const __half2*>(&a.y));
        float2 f2 = __half22float2(*reinterpret_cast<const __half2*>(&a.z));
        float2 f3 = __half22float2(*reinterpret_cast<const __half2*>(&a.w));
        return f0.x*hA.x + f0.y*hA.y + f1.x*hA.z + f1.y*hA.w
             + f2.x*hB.x + f2.y*hB.y + f3.x*hB.z + f3.y*hB.w;
    };

    int kk = 0;
    for (; kk + 8 <= cnt; kk += 8) {
        uint4 a0 = Abase[(size_t)(kk + 0) * (FFq / 8)];
        uint4 a1 = Abase[(size_t)(kk + 1) * (FFq / 8)];
        uint4 a2 = Abase[(size_t)(kk + 2) * (FFq / 8)];
        uint4 a3 = Abase[(size_t)(kk + 3) * (FFq / 8)];
        uint4 a4 = Abase[(size_t)(kk + 4) * (FFq / 8)];
        uint4 a5 = Abase[(size_t)(kk + 5) * (FFq / 8)];
        uint4 a6 = Abase[(size_t)(kk + 6) * (FFq / 8)];
        uint4 a7 = Abase[(size_t)(kk + 7) * (FFq / 8)];
        acc += dot8(a0, kk + 0); acc += dot8(a1, kk + 1);
        acc += dot8(a2, kk + 2); acc += dot8(a3, kk + 3);
        acc += dot8(a4, kk + 4); acc += dot8(a5, kk + 5);
        acc += dot8(a6, kk + 6); acc += dot8(a7, kk + 7);
    }
    for (; kk < cnt; kk++)
        acc += dot8(Abase[(size_t)kk * (FFq / 8)], kk);

    acc += __shfl_xor_sync(0xffffffffu, acc, 1);
    acc += __shfl_xor_sync(0xffffffffu, acc, 2);
    acc += __shfl_xor_sync(0xffffffffu, acc, 4);
    if (q == 0) agg[tr][i] = acc;
    __syncthreads();

    // ---- GRU step 1: x = xold, h = 0 ----
    if (tt < 384) {
        int o = tt % 192, s = tt / 192;
        float a = 0.0f;
#pragma unroll
        for (int j = s * 32; j < s * 32 + 32; j++) a += xold[tr][j] * gk[j * 192 + o];
        pg[tr][0][s][o] = a;
    }
    __syncthreads();
    if (tt < 192)
        xg[tr][tt] = gb[tt] + pg[tr][0][0][tt] + pg[tr][0][1][tt];
    __syncthreads();
    if (tt < Fq) {
        float z = sigm(xg[tr][tt] + grb[tt]);
        float r = sigm(xg[tr][Fq + tt] + grb[Fq + tt]);
        float cand = tanhf(xg[tr][2 * Fq + tt] + r * grb[2 * Fq + tt]);
        h1[tr][tt] = (1.0f - z) * cand;
    }
    __syncthreads();

    // ---- GRU step 2: x = agg, h = h1 ----
    if (tt < 384) {
        int o = tt % 192, s = tt / 192;
        float a = 0.0f, hh = 0.0f;
#pragma unroll
        for (int j = s * 32; j < s * 32 + 32; j++) {
            a  += agg[tr][j] * gk[j * 192 + o];
            hh += h1[tr][j]  * grk[j * 192 + o];
        }
        pg[tr][0][s][o] = a;
        pg[tr][1][s][o] = hh;
    }
    __syncthreads();
    if (tt < 192) {
        xg[tr][tt] = gb[tt]  + pg[tr][0][0][tt] + pg[tr][0][1][tt];
        hg[tr][tt] = grb[tt] + pg[tr][1][0][tt] + pg[tr][1][1][tt];
    }
    __syncthreads();
    if (tt < Fq) {
        float z = sigm(xg[tr][tt] + hg[tr][tt]);
        float r = sigm(xg[tr][Fq + tt] + hg[tr][Fq + tt]);
        float cand = tanhf(xg[tr][2 * Fq + tt] + r * hg[tr][2 * Fq + tt]);
        Hout[(size_t)row * Fq + tt] = z * h1[tr][tt] + (1.0f - z) * cand;
    }
}

// ---------------------------------------------------------------------------
extern "C" void kernel_launch(void* const* d_in, const int* in_sizes, int n_in,
                              void* d_out, int out_size)
{
    const float* X       = (const float*)d_in[0];
    const float* A       = (const float*)d_in[1];
    const float* E       = (const float*)d_in[2];
    const float* W_embed = (const float*)d_in[3];
    const float* b_embed = (const float*)d_in[4];
    const float* W_edge  = (const float*)d_in[5];
    const float* b_edge  = (const float*)d_in[6];
    const float* gk      = (const float*)d_in[7];
    const float* grk     = (const float*)d_in[8];
    const float* gb      = (const float*)d_in[9];
    const float* grb     = (const float*)d_in[10];
    float* out = (float*)d_out;

    float* hbuf = nullptr;
    cudaGetSymbolAddress((void**)&hbuf, g_H);

    k_embed<<<ROWS, 64>>>(X, A, W_embed, b_embed, hbuf);
    k_edge<<<dim3(ROWS / 2, 8), 256>>>(E, W_edge, b_edge);
    k_round<<<ROWS / 2, 1024>>>(hbuf, out,  gk, grk, gb, grb);
    k_round<<<ROWS / 2, 1024>>>(out,  hbuf, gk, grk, gb, grb);
    k_round<<<ROWS / 2, 1024>>>(hbuf, out,  gk, grk, gb, grb);
}

// round 5
// speedup vs baseline: 1.0076x; 1.0076x over previous
#include <cuda_runtime.h>
#include <cuda_fp16.h>
#include <math.h>

constexpr int Bq   = 4;
constexpr int Nq   = 64;
constexpr int Fq   = 64;
constexpr int FINq = 32;
constexpr int EDIMq= 32;
constexpr int FFq  = Fq * Fq;          // 4096
constexpr int ROWS = Bq * Nq;          // 256 target rows (b,n)
constexpr int NGRP = 4;                // edge groups per row

__device__ float  g_H[ROWS * Fq];
__device__ int    g_cnt[ROWS];
__device__ int    g_midx[ROWS * Nq];
__device__ __half g_Amat[(size_t)ROWS * Nq * FFq];     // fp16 edge matrices
__device__ float  g_pagg[NGRP * ROWS * Fq];            // partial aggregates

__device__ __forceinline__ float sigm(float x) { return 1.0f / (1.0f + expf(-x)); }

__device__ __forceinline__ unsigned long long pack2(float lo, float hi) {
    unsigned long long r;
    asm("mov.b64 %0, {%1, %2};" : "=l"(r) : "f"(lo), "f"(hi));
    return r;
}
__device__ __forceinline__ void unpack2(unsigned long long v, float& lo, float& hi) {
    asm("mov.b64 {%0, %1}, %2;" : "=f"(lo), "=f"(hi) : "l"(v));
}
__device__ __forceinline__ unsigned long long ffma2(
    unsigned long long a, unsigned long long b, unsigned long long c) {
    unsigned long long d;
    asm("fma.rn.f32x2 %0, %1, %2, %3;" : "=l"(d) : "l"(a), "l"(b), "l"(c));
    return d;
}

// ---------------------------------------------------------------------------
// Kernel 1: H0 = relu(X@W_embed + b) and per-row mask compaction
// ---------------------------------------------------------------------------
__global__ __launch_bounds__(64) void k_embed(
    const float* __restrict__ X, const float* __restrict__ A,
    const float* __restrict__ W_embed, const float* __restrict__ b_embed,
    float* __restrict__ Hout)
{
    int row = blockIdx.x;
    int t = threadIdx.x;
    __shared__ float xs[FINq];
    if (t < FINq) xs[t] = X[row * FINq + t];
    __syncthreads();

    float acc = b_embed[t];
#pragma unroll
    for (int k = 0; k < FINq; k++) acc += xs[k] * W_embed[k * Fq + t];
    Hout[row * Fq + t] = fmaxf(acc, 0.0f);

    if (t == 0) {
        const float* Arow = A + (size_t)row * Nq;
        int c = 0;
        for (int m = 0; m < Nq; m++)
            if (Arow[m] > 0.5f) g_midx[row * Nq + (c++)] = m;
        g_cnt[row] = c;
    }
}

// ---------------------------------------------------------------------------
// Kernel 2: edge matrices for ACTIVE edges only, packed f32x2 FMA, fp16 out.
// (R3 version — no register spills.)
// ---------------------------------------------------------------------------
__global__ __launch_bounds__(256) void k_edge(
    const float* __restrict__ E, const float* __restrict__ W_edge,
    const float* __restrict__ b_edge)
{
    int rp = blockIdx.x;
    int c0 = blockIdx.y * 512;
    int t  = threadIdx.x;

    __shared__ unsigned long long Es2[2 * Nq][EDIMq];
    __shared__ int   s_slot[2 * Nq];
    __shared__ int   s_ne;

    if (t == 0) {
        int ne = 0;
        for (int r = 0; r < 2; r++) {
            int row = rp * 2 + r;
            int cnt = g_cnt[row];
            for (int k = 0; k < cnt; k++) s_slot[ne++] = row * Nq + k;
        }
        s_ne = ne;
    }
    __syncthreads();
    int ne = s_ne;

    for (int i = t; i < ne * EDIMq; i += 256) {
        int kk = i >> 5, e = i & 31;
        int slot = s_slot[kk];
        int row  = slot >> 6;
        int m    = g_midx[slot];
        float v  = E[((size_t)row * Nq + m) * EDIMq + e];
        Es2[kk][e] = pack2(v, v);
    }
    __syncthreads();

    int cp = c0 + 2 * t;
    unsigned long long w01[EDIMq];
#pragma unroll
    for (int e = 0; e < EDIMq; e++) {
        float2 wv = reinterpret_cast<const float2*>(W_edge + (size_t)e * FFq + cp)[0];
        w01[e] = pack2(wv.x, wv.y);
    }
    float2 bv = reinterpret_cast<const float2*>(b_edge + cp)[0];
    unsigned long long bias01 = pack2(bv.x, bv.y);

    __half2* Aout = reinterpret_cast<__half2*>(g_Amat);
    int cidx = cp >> 1;

    int kk = 0;
    for (; kk + 2 <= ne; kk += 2) {
        unsigned long long acc0 = bias01, acc1 = bias01;
#pragma unroll
        for (int e = 0; e < EDIMq; e++) {
            acc0 = ffma2(Es2[kk][e],     w01[e], acc0);
            acc1 = ffma2(Es2[kk + 1][e], w01[e], acc1);
        }
        float a0, a1, b0v, b1v;
        unpack2(acc0, a0, a1);
        unpack2(acc1, b0v, b1v);
        Aout[(size_t)s_slot[kk]     * (FFq / 2) + cidx] =
            __floats2half2_rn(fmaxf(a0, 0.0f), fmaxf(a1, 0.0f));
        Aout[(size_t)s_slot[kk + 1] * (FFq / 2) + cidx] =
            __floats2half2_rn(fmaxf(b0v, 0.0f), fmaxf(b1v, 0.0f));
    }
    if (kk < ne) {
        unsigned long long acc0 = bias01;
#pragma unroll
        for (int e = 0; e < EDIMq; e++)
            acc0 = ffma2(Es2[kk][e], w01[e], acc0);
        float a0, a1;
        unpack2(acc0, a0, a1);
        Aout[(size_t)s_slot[kk] * (FFq / 2) + cidx] =
            __floats2half2_rn(fmaxf(a0, 0.0f), fmaxf(a1, 0.0f));
    }
}

// ---------------------------------------------------------------------------
// Kernel 3a: partial aggregation. grid = ROWS*NGRP blocks, 256 threads.
// Block (row, g) handles edges kk = g, g+4, g+8, ... (strided -> balanced).
// Thread = i*4 + q loads 2 uint4 (16 fp16) per edge, fully coalesced.
// ---------------------------------------------------------------------------
__global__ __launch_bounds__(256) void k_msg(
    const float* __restrict__ Hin)
{
    int bid = blockIdx.x;
    int row = bid >> 2;
    int g   = bid & 3;
    int b   = row >> 6;
    int t = threadIdx.x;
    int i = t >> 2, q = t & 3;

    int cnt = g_cnt[row];
    int ne = (cnt > g) ? ((cnt - g + NGRP - 1) >> 2) : 0;   // edges this block

    __shared__ float hs[16][Fq];     // up to 16 edges' source states (4KB)

    for (int idx = t; idx < ne * Fq; idx += 256) {
        int e = idx >> 6, j = idx & 63;
        int m = g_midx[row * Nq + g + 4 * e];
        hs[e][j] = Hin[((size_t)b * Nq + m) * Fq + j];
    }
    __syncthreads();

    const uint4* Abase = reinterpret_cast<const uint4*>(g_Amat)
                       + ((size_t)row * Nq + g) * (FFq / 8) + i * 8 + q * 2;
    float acc = 0.0f;
    for (int e = 0; e < ne; e++) {
        uint4 a0 = Abase[(size_t)e * 4 * (FFq / 8)];
        uint4 a1 = Abase[(size_t)e * 4 * (FFq / 8) + 1];
        const float* h = &hs[e][q * 16];
        float2 f;
        f = __half22float2(*reinterpret_cast<const __half2*>(&a0.x)); acc += f.x*h[0] + f.y*h[1];
        f = __half22float2(*reinterpret_cast<const __half2*>(&a0.y)); acc += f.x*h[2] + f.y*h[3];
        f = __half22float2(*reinterpret_cast<const __half2*>(&a0.z)); acc += f.x*h[4] + f.y*h[5];
        f = __half22float2(*reinterpret_cast<const __half2*>(&a0.w)); acc += f.x*h[6] + f.y*h[7];
        f = __half22float2(*reinterpret_cast<const __half2*>(&a1.x)); acc += f.x*h[8] + f.y*h[9];
        f = __half22float2(*reinterpret_cast<const __half2*>(&a1.y)); acc += f.x*h[10] + f.y*h[11];
        f = __half22float2(*reinterpret_cast<const __half2*>(&a1.z)); acc += f.x*h[12] + f.y*h[13];
        f = __half22float2(*reinterpret_cast<const __half2*>(&a1.w)); acc += f.x*h[14] + f.y*h[15];
    }

    acc += __shfl_xor_sync(0xffffffffu, acc, 1);
    acc += __shfl_xor_sync(0xffffffffu, acc, 2);
    if (q == 0) g_pagg[((size_t)g * ROWS + row) * Fq + i] = acc;
}

// ---------------------------------------------------------------------------
// Kernel 3b: reduce partials + 2-step GRU. grid = ROWS, 192 threads.
// xg(step1) and xg(step2) computed in ONE pass over gk (shared weight reads).
// ---------------------------------------------------------------------------
__global__ __launch_bounds__(192) void k_gru(
    const float* __restrict__ Hin, float* __restrict__ Hout,
    const float* __restrict__ gk, const float* __restrict__ grk,
    const float* __restrict__ gb, const float* __restrict__ grb)
{
    int row = blockIdx.x;
    int t = threadIdx.x;

    __shared__ float xold[Fq], aggv[Fq], h1[Fq];
    __shared__ float xg1[3 * Fq], xg2[3 * Fq], hg2[3 * Fq];

    if (t < Fq) {
        xold[t] = Hin[(size_t)row * Fq + t];
        aggv[t] = g_pagg[(size_t)0 * ROWS * Fq + row * Fq + t]
                + g_pagg[(size_t)1 * ROWS * Fq + row * Fq + t]
                + g_pagg[(size_t)2 * ROWS * Fq + row * Fq + t]
                + g_pagg[(size_t)3 * ROWS * Fq + row * Fq + t];
    }
    __syncthreads();

    // one pass over gk computes both steps' input gates
    {
        float a1 = gb[t], a2 = gb[t];
#pragma unroll 8
        for (int j = 0; j < Fq; j++) {
            float w = gk[j * 192 + t];
            a1 += xold[j] * w;
            a2 += aggv[j] * w;
        }
        xg1[t] = a1;
        xg2[t] = a2;
    }
    __syncthreads();

    if (t < Fq) {
        float z = sigm(xg1[t] + grb[t]);
        float r = sigm(xg1[Fq + t] + grb[Fq + t]);
        float cand = tanhf(xg1[2 * Fq + t] + r * grb[2 * Fq + t]);
        h1[t] = (1.0f - z) * cand;
    }
    __syncthreads();

    {
        float hh = grb[t];
#pragma unroll 8
        for (int j = 0; j < Fq; j++) hh += h1[j] * grk[j * 192 + t];
        hg2[t] = hh;
    }
    __syncthreads();

    if (t < Fq) {
        float z = sigm(xg2[t] + hg2[t]);
        float r = sigm(xg2[Fq + t] + hg2[Fq + t]);
        float cand = tanhf(xg2[2 * Fq + t] + r * hg2[2 * Fq + t]);
        Hout[(size_t)row * Fq + t] = z * h1[t] + (1.0f - z) * cand;
    }
}

// ---------------------------------------------------------------------------
extern "C" void kernel_launch(void* const* d_in, const int* in_sizes, int n_in,
                              void* d_out, int out_size)
{
    const float* X       = (const float*)d_in[0];
    const float* A       = (const float*)d_in[1];
    const float* E       = (const float*)d_in[2];
    const float* W_embed = (const float*)d_in[3];
    const float* b_embed = (const float*)d_in[4];
    const float* W_edge  = (const float*)d_in[5];
    const float* b_edge  = (const float*)d_in[6];
    const float* gk      = (const float*)d_in[7];
    const float* grk     = (const float*)d_in[8];
    const float* gb      = (const float*)d_in[9];
    const float* grb     = (const float*)d_in[10];
    float* out = (float*)d_out;

    float* hbuf = nullptr;
    cudaGetSymbolAddress((void**)&hbuf, g_H);

    k_embed<<<ROWS, 64>>>(X, A, W_embed, b_embed, hbuf);
    k_edge<<<dim3(ROWS / 2, 8), 256>>>(E, W_edge, b_edge);

    k_msg<<<ROWS * NGRP, 256>>>(hbuf);
    k_gru<<<ROWS, 192>>>(hbuf, out, gk, grk, gb, grb);

    k_msg<<<ROWS * NGRP, 256>>>(out);
    k_gru<<<ROWS, 192>>>(out, hbuf, gk, grk, gb, grb);

    k_msg<<<ROWS * NGRP, 256>>>(hbuf);
    k_gru<<<ROWS, 192>>>(hbuf, out, gk, grk, gb, grb);
}

// round 6
// speedup vs baseline: 1.0518x; 1.0439x over previous
#include <cuda_runtime.h>
#include <cuda_fp16.h>
#include <math.h>

constexpr int Bq   = 4;
constexpr int Nq   = 64;
constexpr int Fq   = 64;
constexpr int FINq = 32;
constexpr int EDIMq= 32;
constexpr int FFq  = Fq * Fq;          // 4096
constexpr int ROWS = Bq * Nq;          // 256 target rows (b,n)

__device__ float  g_H[ROWS * Fq];
__device__ float  g_H2[ROWS * Fq];
__device__ int    g_cnt[ROWS];
__device__ int    g_midx[ROWS * Nq];
__device__ __half g_Amat[(size_t)ROWS * Nq * FFq];     // fp16 edge matrices

__device__ int          g_bar_count = 0;
__device__ volatile int g_bar_gen   = 0;

__device__ __forceinline__ float sigm(float x) { return 1.0f / (1.0f + expf(-x)); }

__device__ __forceinline__ unsigned long long pack2(float lo, float hi) {
    unsigned long long r;
    asm("mov.b64 %0, {%1, %2};" : "=l"(r) : "f"(lo), "f"(hi));
    return r;
}
__device__ __forceinline__ void unpack2(unsigned long long v, float& lo, float& hi) {
    asm("mov.b64 {%0, %1}, %2;" : "=f"(lo), "=f"(hi) : "l"(v));
}
__device__ __forceinline__ unsigned long long ffma2(
    unsigned long long a, unsigned long long b, unsigned long long c) {
    unsigned long long d;
    asm("fma.rn.f32x2 %0, %1, %2, %3;" : "=l"(d) : "l"(a), "l"(b), "l"(c));
    return d;
}

// grid-wide software barrier (all blocks co-resident by construction)
__device__ __forceinline__ void grid_barrier(int nblocks) {
    __syncthreads();
    if (threadIdx.x == 0) {
        __threadfence();
        int gen = g_bar_gen;
        if (atomicAdd(&g_bar_count, 1) == nblocks - 1) {
            g_bar_count = 0;
            __threadfence();
            g_bar_gen = gen + 1;
        } else {
            while (g_bar_gen == gen) { }
        }
    }
    __syncthreads();
}

// ---------------------------------------------------------------------------
// Kernel 1: H0 = relu(X@W_embed + b) and per-row mask compaction
// ---------------------------------------------------------------------------
__global__ __launch_bounds__(64) void k_embed(
    const float* __restrict__ X, const float* __restrict__ A,
    const float* __restrict__ W_embed, const float* __restrict__ b_embed,
    float* __restrict__ Hout)
{
    int row = blockIdx.x;
    int t = threadIdx.x;
    __shared__ float xs[FINq];
    if (t < FINq) xs[t] = X[row * FINq + t];
    __syncthreads();

    float acc = b_embed[t];
#pragma unroll
    for (int k = 0; k < FINq; k++) acc += xs[k] * W_embed[k * Fq + t];
    Hout[row * Fq + t] = fmaxf(acc, 0.0f);

    if (t == 0) {
        const float* Arow = A + (size_t)row * Nq;
        int c = 0;
        for (int m = 0; m < Nq; m++)
            if (Arow[m] > 0.5f) g_midx[row * Nq + (c++)] = m;
        g_cnt[row] = c;
    }
}

// ---------------------------------------------------------------------------
// Kernel 2: edge matrices for ACTIVE edges only, packed f32x2 FMA, fp16 out.
// ---------------------------------------------------------------------------
__global__ __launch_bounds__(256) void k_edge(
    const float* __restrict__ E, const float* __restrict__ W_edge,
    const float* __restrict__ b_edge)
{
    int rp = blockIdx.x;
    int c0 = blockIdx.y * 512;
    int t  = threadIdx.x;

    __shared__ unsigned long long Es2[2 * Nq][EDIMq];
    __shared__ int   s_slot[2 * Nq];
    __shared__ int   s_ne;

    if (t == 0) {
        int ne = 0;
        for (int r = 0; r < 2; r++) {
            int row = rp * 2 + r;
            int cnt = g_cnt[row];
            for (int k = 0; k < cnt; k++) s_slot[ne++] = row * Nq + k;
        }
        s_ne = ne;
    }
    __syncthreads();
    int ne = s_ne;

    for (int i = t; i < ne * EDIMq; i += 256) {
        int kk = i >> 5, e = i & 31;
        int slot = s_slot[kk];
        int row  = slot >> 6;
        int m    = g_midx[slot];
        float v  = E[((size_t)row * Nq + m) * EDIMq + e];
        Es2[kk][e] = pack2(v, v);
    }
    __syncthreads();

    int cp = c0 + 2 * t;
    unsigned long long w01[EDIMq];
#pragma unroll
    for (int e = 0; e < EDIMq; e++) {
        float2 wv = reinterpret_cast<const float2*>(W_edge + (size_t)e * FFq + cp)[0];
        w01[e] = pack2(wv.x, wv.y);
    }
    float2 bv = reinterpret_cast<const float2*>(b_edge + cp)[0];
    unsigned long long bias01 = pack2(bv.x, bv.y);

    __half2* Aout = reinterpret_cast<__half2*>(g_Amat);
    int cidx = cp >> 1;

    int kk = 0;
    for (; kk + 2 <= ne; kk += 2) {
        unsigned long long acc0 = bias01, acc1 = bias01;
#pragma unroll
        for (int e = 0; e < EDIMq; e++) {
            acc0 = ffma2(Es2[kk][e],     w01[e], acc0);
            acc1 = ffma2(Es2[kk + 1][e], w01[e], acc1);
        }
        float a0, a1, b0v, b1v;
        unpack2(acc0, a0, a1);
        unpack2(acc1, b0v, b1v);
        Aout[(size_t)s_slot[kk]     * (FFq / 2) + cidx] =
            __floats2half2_rn(fmaxf(a0, 0.0f), fmaxf(a1, 0.0f));
        Aout[(size_t)s_slot[kk + 1] * (FFq / 2) + cidx] =
            __floats2half2_rn(fmaxf(b0v, 0.0f), fmaxf(b1v, 0.0f));
    }
    if (kk < ne) {
        unsigned long long acc0 = bias01;
#pragma unroll
        for (int e = 0; e < EDIMq; e++)
            acc0 = ffma2(Es2[kk][e], w01[e], acc0);
        float a0, a1;
        unpack2(acc0, a0, a1);
        Aout[(size_t)s_slot[kk] * (FFq / 2) + cidx] =
            __floats2half2_rn(fmaxf(a0, 0.0f), fmaxf(a1, 0.0f));
    }
}

// ---------------------------------------------------------------------------
// Kernel 3: ALL 3 rounds in one persistent kernel (256 blocks x 256 threads,
// 2 blocks/SM guaranteed resident -> software grid barrier is safe).
// Block owns one row. Per round: stage sources -> aggregate -> fused GRU.
// Cross-round H reads use __ldcg (L2) since L1 is not coherent across blocks.
// ---------------------------------------------------------------------------
__global__ __launch_bounds__(256, 2) void k_rounds(
    const float* __restrict__ gk, const float* __restrict__ grk,
    const float* __restrict__ gb, const float* __restrict__ grb,
    float* __restrict__ out)
{
    int row = blockIdx.x;
    int b = row >> 6;
    int t = threadIdx.x;
    int i = t >> 2, q = t & 3;

    __shared__ float hs[Nq][Fq];                 // 16KB staged sources
    __shared__ float xold[Fq], aggv[Fq], h1[Fq];
    __shared__ float xg1[3 * Fq], xg2[3 * Fq], hg2[3 * Fq];

    int cnt = g_cnt[row];
    const uint4* Abase = reinterpret_cast<const uint4*>(g_Amat)
                       + (size_t)row * Nq * (FFq / 8) + i * 8 + q * 2;

    for (int r = 0; r < 3; r++) {
        const float* Hin = (r == 0) ? g_H : ((r == 1) ? g_H2 : g_H);
        float* Hout = (r == 0) ? g_H2 : ((r == 1) ? g_H : out);

        // stage active source states (L2 loads, bypass L1)
        for (int idx = t; idx < cnt * Fq; idx += 256) {
            int e = idx >> 6, j = idx & 63;
            int m = g_midx[row * Nq + e];
            hs[e][j] = __ldcg(&Hin[((size_t)b * Nq + m) * Fq + j]);
        }
        if (t < Fq) xold[t] = __ldcg(&Hin[(size_t)row * Fq + t]);
        __syncthreads();

        // ---- aggregation: thread (i,q), 16 halves per edge ----
        float acc = 0.0f;
        auto edot = [&](int e) {
            uint4 a0 = Abase[(size_t)e * (FFq / 8)];
            uint4 a1 = Abase[(size_t)e * (FFq / 8) + 1];
            const float* h = &hs[e][q * 16];
            float s = 0.0f; float2 f;
            f = __half22float2(*reinterpret_cast<const __half2*>(&a0.x)); s += f.x*h[0]  + f.y*h[1];
            f = __half22float2(*reinterpret_cast<const __half2*>(&a0.y)); s += f.x*h[2]  + f.y*h[3];
            f = __half22float2(*reinterpret_cast<const __half2*>(&a0.z)); s += f.x*h[4]  + f.y*h[5];
            f = __half22float2(*reinterpret_cast<const __half2*>(&a0.w)); s += f.x*h[6]  + f.y*h[7];
            f = __half22float2(*reinterpret_cast<const __half2*>(&a1.x)); s += f.x*h[8]  + f.y*h[9];
            f = __half22float2(*reinterpret_cast<const __half2*>(&a1.y)); s += f.x*h[10] + f.y*h[11];
            f = __half22float2(*reinterpret_cast<const __half2*>(&a1.z)); s += f.x*h[12] + f.y*h[13];
            f = __half22float2(*reinterpret_cast<const __half2*>(&a1.w)); s += f.x*h[14] + f.y*h[15];
            return s;
        };
        int e = 0;
        for (; e + 4 <= cnt; e += 4) {
            acc += edot(e) + edot(e + 1) + edot(e + 2) + edot(e + 3);
        }
        for (; e < cnt; e++) acc += edot(e);

        acc += __shfl_xor_sync(0xffffffffu, acc, 1);
        acc += __shfl_xor_sync(0xffffffffu, acc, 2);
        if (q == 0) aggv[i] = acc;
        __syncthreads();

        // ---- GRU: one pass over gk computes both steps' input gates ----
        if (t < 192) {
            float a1 = gb[t], a2 = gb[t];
#pragma unroll 8
            for (int j = 0; j < Fq; j++) {
                float w = gk[j * 192 + t];
                a1 += xold[j] * w;
                a2 += aggv[j] * w;
            }
            xg1[t] = a1;
            xg2[t] = a2;
        }
        __syncthreads();
        if (t < Fq) {
            float z = sigm(xg1[t] + grb[t]);
            float rr = sigm(xg1[Fq + t] + grb[Fq + t]);
            float cand = tanhf(xg1[2 * Fq + t] + rr * grb[2 * Fq + t]);
            h1[t] = (1.0f - z) * cand;
        }
        __syncthreads();
        if (t < 192) {
            float hh = grb[t];
#pragma unroll 8
            for (int j = 0; j < Fq; j++) hh += h1[j] * grk[j * 192 + t];
            hg2[t] = hh;
        }
        __syncthreads();
        if (t < Fq) {
            float z = sigm(xg2[t] + hg2[t]);
            float rr = sigm(xg2[Fq + t] + hg2[Fq + t]);
            float cand = tanhf(xg2[2 * Fq + t] + rr * hg2[2 * Fq + t]);
            Hout[(size_t)row * Fq + t] = z * h1[t] + (1.0f - z) * cand;
        }

        if (r < 2) grid_barrier(ROWS);
    }
}

// ---------------------------------------------------------------------------
extern "C" void kernel_launch(void* const* d_in, const int* in_sizes, int n_in,
                              void* d_out, int out_size)
{
    const float* X       = (const float*)d_in[0];
    const float* A       = (const float*)d_in[1];
    const float* E       = (const float*)d_in[2];
    const float* W_embed = (const float*)d_in[3];
    const float* b_embed = (const float*)d_in[4];
    const float* W_edge  = (const float*)d_in[5];
    const float* b_edge  = (const float*)d_in[6];
    const float* gk      = (const float*)d_in[7];
    const float* grk     = (const float*)d_in[8];
    const float* gb      = (const float*)d_in[9];
    const float* grb     = (const float*)d_in[10];
    float* out = (float*)d_out;

    float* hbuf = nullptr;
    cudaGetSymbolAddress((void**)&hbuf, g_H);

    k_embed<<<ROWS, 64>>>(X, A, W_embed, b_embed, hbuf);
    k_edge<<<dim3(ROWS / 2, 8), 256>>>(E, W_edge, b_edge);
    k_rounds<<<ROWS, 256>>>(gk, grk, gb, grb, out);
}